// round 2
// baseline (speedup 1.0000x reference)
#include <cuda_runtime.h>
#include <math.h>

// Problem constants
#define C_DIM   256
#define M_DIM   512
#define HW_DIM  4096      // 64*64
#define N_IMG   16
#define TB      64        // tokens per block
#define THREADS 256
#define CCHUNK  64        // c-chunk for GEMM1 tiles
#define SROW    513       // padded score row (avoids 512-stride bank conflicts)

// Normalized memory (after MLP), computed by kernel 1.
__device__ float g_mem_norm[M_DIM * C_DIM];

// ---------------------------------------------------------------------------
// Kernel 1: per-slot MLP (Linear->ReLU->Linear->ReLU) + L2 normalize.
// One block per memory slot. Trivial cost (512 slots x 64K FMA).
// ---------------------------------------------------------------------------
__global__ void mem_mlp_kernel(const float* __restrict__ memory,
                               const float* __restrict__ w1,
                               const float* __restrict__ b1,
                               const float* __restrict__ w2,
                               const float* __restrict__ b2) {
    __shared__ float srow[C_DIM];
    __shared__ float h[C_DIM / 2];
    __shared__ float red[THREADS];
    const int m   = blockIdx.x;
    const int tid = threadIdx.x;

    srow[tid] = memory[m * C_DIM + tid];
    __syncthreads();

    if (tid < 128) {
        float acc = b1[tid];
#pragma unroll 8
        for (int c = 0; c < C_DIM; c++) acc += srow[c] * w1[c * 128 + tid];
        h[tid] = fmaxf(acc, 0.0f);
    }
    __syncthreads();

    float acc = b2[tid];
#pragma unroll 8
    for (int j = 0; j < 128; j++) acc += h[j] * w2[j * C_DIM + tid];
    acc = fmaxf(acc, 0.0f);

    red[tid] = acc * acc;
    __syncthreads();
#pragma unroll
    for (int s = 128; s > 0; s >>= 1) {
        if (tid < s) red[tid] += red[tid + s];
        __syncthreads();
    }
    const float inv = 1.0f / fmaxf(sqrtf(red[0]), 1e-12f);
    g_mem_norm[m * C_DIM + tid] = acc * inv;
}

// ---------------------------------------------------------------------------
// Kernel 2: fused per-token-tile pipeline.
//   x tile load (coalesced along hw) -> L2-normalize tokens
//   GEMM1 scores[64][512] (register 4x4 tiles, smem mem tiles)
//   softmax + hardshrink + L1 renorm (in smem)
//   att_map write (transposed, coalesced) + GEMM2 out = att @ mem_norm
// ---------------------------------------------------------------------------
__global__ __launch_bounds__(THREADS)
void fused_attn_kernel(const float* __restrict__ x,
                       float* __restrict__ out,
                       float* __restrict__ attmap) {
    extern __shared__ float smem[];
    float* scores = smem;                         // TB * SROW        (64*513)
    float* xs     = smem + TB * SROW;             // C * TB (reused as ms2 in GEMM2)
    float* msA    = xs + C_DIM * TB;              // 64 * CCHUNK
    float* invn   = msA + 64 * CCHUNK;            // TB

    const int tid = threadIdx.x;
    const int b   = blockIdx.x;
    const int n   = b >> 6;            // 64 blocks per image (4096/64 tokens)
    const int hw0 = (b & 63) << 6;

    const float* xbase = x + (size_t)n * C_DIM * HW_DIM + hw0;

    // ---- load x tile: xs[c][t], coalesced along t -------------------------
#pragma unroll 4
    for (int idx = tid; idx < C_DIM * TB; idx += THREADS) {
        const int c = idx >> 6, t = idx & 63;
        xs[c * TB + t] = xbase[(size_t)c * HW_DIM + t];
    }
    __syncthreads();

    // ---- per-token L2 norm ------------------------------------------------
    if (tid < TB) {
        float ss = 0.0f;
#pragma unroll 8
        for (int c = 0; c < C_DIM; c++) {
            const float v = xs[c * TB + tid];
            ss += v * v;
        }
        invn[tid] = 1.0f / fmaxf(sqrtf(ss), 1e-12f);
    }
    __syncthreads();
#pragma unroll 4
    for (int idx = tid; idx < C_DIM * TB; idx += THREADS) {
        xs[idx] *= invn[idx & 63];
    }
    __syncthreads();

    // ---- GEMM1: scores[t][m] = x_norm . mem_norm[m] ------------------------
    const int tIdx = tid & 15;   // 16 token groups
    const int mIdx = tid >> 4;   // 16 slot groups
    const int t0   = tIdx * 4;
    const int m0   = mIdx * 4;

    for (int mo = 0; mo < M_DIM; mo += 64) {
        float acc[4][4] = {};
        for (int co = 0; co < C_DIM; co += CCHUNK) {
            __syncthreads();
            // load msA[m][cc] (64 x 64), LDG coalesced along cc
#pragma unroll 4
            for (int idx = tid; idx < 64 * CCHUNK; idx += THREADS) {
                const int mm = idx >> 6, cc = idx & 63;
                msA[idx] = g_mem_norm[(mo + mm) * C_DIM + co + cc];
            }
            __syncthreads();
#pragma unroll 8
            for (int cc = 0; cc < CCHUNK; cc++) {
                const float4 xv = *(const float4*)&xs[(co + cc) * TB + t0];
                const float a0 = msA[(m0 + 0) * CCHUNK + cc];
                const float a1 = msA[(m0 + 1) * CCHUNK + cc];
                const float a2 = msA[(m0 + 2) * CCHUNK + cc];
                const float a3 = msA[(m0 + 3) * CCHUNK + cc];
                acc[0][0] += xv.x * a0; acc[0][1] += xv.x * a1;
                acc[0][2] += xv.x * a2; acc[0][3] += xv.x * a3;
                acc[1][0] += xv.y * a0; acc[1][1] += xv.y * a1;
                acc[1][2] += xv.y * a2; acc[1][3] += xv.y * a3;
                acc[2][0] += xv.z * a0; acc[2][1] += xv.z * a1;
                acc[2][2] += xv.z * a2; acc[2][3] += xv.z * a3;
                acc[3][0] += xv.w * a0; acc[3][1] += xv.w * a1;
                acc[3][2] += xv.w * a2; acc[3][3] += xv.w * a3;
            }
        }
#pragma unroll
        for (int i = 0; i < 4; i++)
#pragma unroll
            for (int j = 0; j < 4; j++)
                scores[(t0 + i) * SROW + mo + m0 + j] = acc[i][j];
    }
    __syncthreads();

    // ---- softmax + hardshrink + L1 renorm (one warp handles 8 tokens) ------
    const int warp = tid >> 5, lane = tid & 31;
    for (int r = 0; r < 8; r++) {
        const int t = warp * 8 + r;
        float* row = scores + t * SROW;

        float mx = -1e30f;
#pragma unroll
        for (int k = 0; k < 16; k++) mx = fmaxf(mx, row[lane + 32 * k]);
#pragma unroll
        for (int o = 16; o > 0; o >>= 1) mx = fmaxf(mx, __shfl_xor_sync(0xffffffffu, mx, o));

        float s = 0.0f;
#pragma unroll
        for (int k = 0; k < 16; k++) {
            const float v = __expf(row[lane + 32 * k] - mx);
            row[lane + 32 * k] = v;
            s += v;
        }
#pragma unroll
        for (int o = 16; o > 0; o >>= 1) s += __shfl_xor_sync(0xffffffffu, s, o);
        const float invs = 1.0f / s;   // s >= 1 always (max term)

        float as = 0.0f;
#pragma unroll
        for (int k = 0; k < 16; k++) {
            const float a = fmaxf(row[lane + 32 * k] * invs - 0.0025f, 0.0f);
            row[lane + 32 * k] = a;
            as += a;
        }
#pragma unroll
        for (int o = 16; o > 0; o >>= 1) as += __shfl_xor_sync(0xffffffffu, as, o);
        const float inva = 1.0f / fmaxf(as, 1e-12f);
#pragma unroll
        for (int k = 0; k < 16; k++) row[lane + 32 * k] *= inva;
    }
    __syncthreads();

    // ---- write att_map [n, m, h, w], coalesced along t ---------------------
    float* attb = attmap + (size_t)n * M_DIM * HW_DIM + hw0;
#pragma unroll 4
    for (int idx = tid; idx < M_DIM * TB; idx += THREADS) {
        const int t = idx & 63, mm = idx >> 6;
        attb[(size_t)mm * HW_DIM + t] = scores[t * SROW + mm];
    }

    // ---- GEMM2: out[t][c] = sum_m att[t][m] * mem_norm[m][c] ---------------
    float* ms2 = xs;                  // reuse xs region: [32][256]
    const int cIdx = tid >> 4;        // 0..15
    const int c0   = cIdx * 16;

    float acc2[4][16] = {};
    for (int mo = 0; mo < M_DIM; mo += 32) {
        __syncthreads();
#pragma unroll 4
        for (int idx = tid; idx < 32 * C_DIM; idx += THREADS) {
            const int cc = idx & 255, mk = idx >> 8;
            ms2[mk * C_DIM + cc] = g_mem_norm[(mo + mk) * C_DIM + cc];
        }
        __syncthreads();
#pragma unroll 4
        for (int mk = 0; mk < 32; mk++) {
            const float a0 = scores[(t0 + 0) * SROW + mo + mk];
            const float a1 = scores[(t0 + 1) * SROW + mo + mk];
            const float a2 = scores[(t0 + 2) * SROW + mo + mk];
            const float a3 = scores[(t0 + 3) * SROW + mo + mk];
            const float* mrow = ms2 + mk * C_DIM + c0;
#pragma unroll
            for (int j4 = 0; j4 < 4; j4++) {
                const float4 mv = *(const float4*)&mrow[j4 * 4];
                acc2[0][j4 * 4 + 0] += a0 * mv.x; acc2[0][j4 * 4 + 1] += a0 * mv.y;
                acc2[0][j4 * 4 + 2] += a0 * mv.z; acc2[0][j4 * 4 + 3] += a0 * mv.w;
                acc2[1][j4 * 4 + 0] += a1 * mv.x; acc2[1][j4 * 4 + 1] += a1 * mv.y;
                acc2[1][j4 * 4 + 2] += a1 * mv.z; acc2[1][j4 * 4 + 3] += a1 * mv.w;
                acc2[2][j4 * 4 + 0] += a2 * mv.x; acc2[2][j4 * 4 + 1] += a2 * mv.y;
                acc2[2][j4 * 4 + 2] += a2 * mv.z; acc2[2][j4 * 4 + 3] += a2 * mv.w;
                acc2[3][j4 * 4 + 0] += a3 * mv.x; acc2[3][j4 * 4 + 1] += a3 * mv.y;
                acc2[3][j4 * 4 + 2] += a3 * mv.z; acc2[3][j4 * 4 + 3] += a3 * mv.w;
            }
        }
    }

    // ---- write output [n, c, h, w]: 4 consecutive tokens -> float4 ---------
    float* ob = out + (size_t)n * C_DIM * HW_DIM + hw0;
#pragma unroll
    for (int j = 0; j < 16; j++) {
        const float4 v = make_float4(acc2[0][j], acc2[1][j], acc2[2][j], acc2[3][j]);
        *(float4*)&ob[(size_t)(c0 + j) * HW_DIM + t0] = v;
    }
}

// ---------------------------------------------------------------------------
extern "C" void kernel_launch(void* const* d_in, const int* in_sizes, int n_in,
                              void* d_out, int out_size) {
    const float* x      = (const float*)d_in[0];  // [16,256,64,64]
    const float* memory = (const float*)d_in[1];  // [512,256]
    const float* w1     = (const float*)d_in[2];  // [256,128]
    const float* b1     = (const float*)d_in[3];  // [128]
    const float* w2     = (const float*)d_in[4];  // [128,256]
    const float* b2     = (const float*)d_in[5];  // [256]

    float* out    = (float*)d_out;                              // [16,256,64,64]
    float* attmap = out + (size_t)N_IMG * C_DIM * HW_DIM;       // [16,512,64,64]

    mem_mlp_kernel<<<M_DIM, THREADS>>>(memory, w1, b1, w2, b2);

    const size_t smem_bytes =
        (size_t)(TB * SROW + C_DIM * TB + 64 * CCHUNK + TB) * sizeof(float);
    cudaFuncSetAttribute(fused_attn_kernel,
                         cudaFuncAttributeMaxDynamicSharedMemorySize,
                         (int)smem_bytes);

    const int tiles = (N_IMG * HW_DIM) / TB;  // 1024
    fused_attn_kernel<<<tiles, THREADS, smem_bytes>>>(x, out, attmap);
}

// round 3
// speedup vs baseline: 1.0010x; 1.0010x over previous
#include <cuda_runtime.h>
#include <math.h>

// Problem constants
#define C_DIM   256
#define M_DIM   512
#define HW_DIM  4096      // 64*64
#define N_IMG   16
#define TB      64        // tokens per block
#define THREADS 256
#define CCHUNK  64        // c-chunk for GEMM1 tiles
#define SROW    513       // padded score row (avoids 512-stride bank conflicts)

// Normalized memory (after MLP), computed by kernel 1.
__device__ float g_mem_norm[M_DIM * C_DIM];

// ---------------------------------------------------------------------------
// Kernel 1: per-slot MLP (Linear->ReLU->Linear->ReLU) + L2 normalize.
// One block per memory slot. Trivial cost (512 slots x 64K FMA).
// ---------------------------------------------------------------------------
__global__ void mem_mlp_kernel(const float* __restrict__ memory,
                               const float* __restrict__ w1,
                               const float* __restrict__ b1,
                               const float* __restrict__ w2,
                               const float* __restrict__ b2) {
    __shared__ float srow[C_DIM];
    __shared__ float h[C_DIM / 2];
    __shared__ float red[THREADS];
    const int m   = blockIdx.x;
    const int tid = threadIdx.x;

    srow[tid] = memory[m * C_DIM + tid];
    __syncthreads();

    if (tid < 128) {
        float acc = b1[tid];
#pragma unroll 8
        for (int c = 0; c < C_DIM; c++) acc += srow[c] * w1[c * 128 + tid];
        h[tid] = fmaxf(acc, 0.0f);
    }
    __syncthreads();

    float acc = b2[tid];
#pragma unroll 8
    for (int j = 0; j < 128; j++) acc += h[j] * w2[j * C_DIM + tid];
    acc = fmaxf(acc, 0.0f);

    red[tid] = acc * acc;
    __syncthreads();
#pragma unroll
    for (int s = 128; s > 0; s >>= 1) {
        if (tid < s) red[tid] += red[tid + s];
        __syncthreads();
    }
    const float inv = 1.0f / fmaxf(sqrtf(red[0]), 1e-12f);
    g_mem_norm[m * C_DIM + tid] = acc * inv;
}

// ---------------------------------------------------------------------------
// Kernel 2: fused per-token-tile pipeline.
//   x tile load (coalesced along hw) -> L2-normalize tokens
//   GEMM1 scores[64][512] (register 4x4 tiles, smem mem tiles)
//   softmax + hardshrink + L1 renorm (in smem)
//   att_map write (transposed, coalesced) + GEMM2 out = att @ mem_norm
// ---------------------------------------------------------------------------
__global__ __launch_bounds__(THREADS)
void fused_attn_kernel(const float* __restrict__ x,
                       float* __restrict__ out,
                       float* __restrict__ attmap) {
    extern __shared__ float smem[];
    float* scores = smem;                         // TB * SROW        (64*513)
    float* xs     = smem + TB * SROW;             // C * TB (reused as ms2 in GEMM2)
    float* msA    = xs + C_DIM * TB;              // 64 * CCHUNK
    float* invn   = msA + 64 * CCHUNK;            // TB

    const int tid = threadIdx.x;
    const int b   = blockIdx.x;
    const int n   = b >> 6;            // 64 blocks per image (4096/64 tokens)
    const int hw0 = (b & 63) << 6;

    const float* xbase = x + (size_t)n * C_DIM * HW_DIM + hw0;

    // ---- load x tile: xs[c][t], coalesced along t -------------------------
#pragma unroll 4
    for (int idx = tid; idx < C_DIM * TB; idx += THREADS) {
        const int c = idx >> 6, t = idx & 63;
        xs[c * TB + t] = xbase[(size_t)c * HW_DIM + t];
    }
    __syncthreads();

    // ---- per-token L2 norm ------------------------------------------------
    if (tid < TB) {
        float ss = 0.0f;
#pragma unroll 8
        for (int c = 0; c < C_DIM; c++) {
            const float v = xs[c * TB + tid];
            ss += v * v;
        }
        invn[tid] = 1.0f / fmaxf(sqrtf(ss), 1e-12f);
    }
    __syncthreads();
#pragma unroll 4
    for (int idx = tid; idx < C_DIM * TB; idx += THREADS) {
        xs[idx] *= invn[idx & 63];
    }
    __syncthreads();

    // ---- GEMM1: scores[t][m] = x_norm . mem_norm[m] ------------------------
    const int tIdx = tid & 15;   // 16 token groups
    const int mIdx = tid >> 4;   // 16 slot groups
    const int t0   = tIdx * 4;
    const int m0   = mIdx * 4;

    for (int mo = 0; mo < M_DIM; mo += 64) {
        float acc[4][4] = {};
        for (int co = 0; co < C_DIM; co += CCHUNK) {
            __syncthreads();
            // load msA[m][cc] (64 x 64), LDG coalesced along cc
#pragma unroll 4
            for (int idx = tid; idx < 64 * CCHUNK; idx += THREADS) {
                const int mm = idx >> 6, cc = idx & 63;
                msA[idx] = g_mem_norm[(mo + mm) * C_DIM + co + cc];
            }
            __syncthreads();
#pragma unroll 8
            for (int cc = 0; cc < CCHUNK; cc++) {
                const float4 xv = *(const float4*)&xs[(co + cc) * TB + t0];
                const float a0 = msA[(m0 + 0) * CCHUNK + cc];
                const float a1 = msA[(m0 + 1) * CCHUNK + cc];
                const float a2 = msA[(m0 + 2) * CCHUNK + cc];
                const float a3 = msA[(m0 + 3) * CCHUNK + cc];
                acc[0][0] += xv.x * a0; acc[0][1] += xv.x * a1;
                acc[0][2] += xv.x * a2; acc[0][3] += xv.x * a3;
                acc[1][0] += xv.y * a0; acc[1][1] += xv.y * a1;
                acc[1][2] += xv.y * a2; acc[1][3] += xv.y * a3;
                acc[2][0] += xv.z * a0; acc[2][1] += xv.z * a1;
                acc[2][2] += xv.z * a2; acc[2][3] += xv.z * a3;
                acc[3][0] += xv.w * a0; acc[3][1] += xv.w * a1;
                acc[3][2] += xv.w * a2; acc[3][3] += xv.w * a3;
            }
        }
#pragma unroll
        for (int i = 0; i < 4; i++)
#pragma unroll
            for (int j = 0; j < 4; j++)
                scores[(t0 + i) * SROW + mo + m0 + j] = acc[i][j];
    }
    __syncthreads();

    // ---- softmax + hardshrink + L1 renorm (one warp handles 8 tokens) ------
    const int warp = tid >> 5, lane = tid & 31;
    for (int r = 0; r < 8; r++) {
        const int t = warp * 8 + r;
        float* row = scores + t * SROW;

        float mx = -1e30f;
#pragma unroll
        for (int k = 0; k < 16; k++) mx = fmaxf(mx, row[lane + 32 * k]);
#pragma unroll
        for (int o = 16; o > 0; o >>= 1) mx = fmaxf(mx, __shfl_xor_sync(0xffffffffu, mx, o));

        float s = 0.0f;
#pragma unroll
        for (int k = 0; k < 16; k++) {
            const float v = __expf(row[lane + 32 * k] - mx);
            row[lane + 32 * k] = v;
            s += v;
        }
#pragma unroll
        for (int o = 16; o > 0; o >>= 1) s += __shfl_xor_sync(0xffffffffu, s, o);
        const float invs = 1.0f / s;   // s >= 1 always (max term)

        float as = 0.0f;
#pragma unroll
        for (int k = 0; k < 16; k++) {
            const float a = fmaxf(row[lane + 32 * k] * invs - 0.0025f, 0.0f);
            row[lane + 32 * k] = a;
            as += a;
        }
#pragma unroll
        for (int o = 16; o > 0; o >>= 1) as += __shfl_xor_sync(0xffffffffu, as, o);
        const float inva = 1.0f / fmaxf(as, 1e-12f);
#pragma unroll
        for (int k = 0; k < 16; k++) row[lane + 32 * k] *= inva;
    }
    __syncthreads();

    // ---- write att_map [n, m, h, w], coalesced along t ---------------------
    float* attb = attmap + (size_t)n * M_DIM * HW_DIM + hw0;
#pragma unroll 4
    for (int idx = tid; idx < M_DIM * TB; idx += THREADS) {
        const int t = idx & 63, mm = idx >> 6;
        attb[(size_t)mm * HW_DIM + t] = scores[t * SROW + mm];
    }

    // ---- GEMM2: out[t][c] = sum_m att[t][m] * mem_norm[m][c] ---------------
    float* ms2 = xs;                  // reuse xs region: [32][256]
    const int cIdx = tid >> 4;        // 0..15
    const int c0   = cIdx * 16;

    float acc2[4][16] = {};
    for (int mo = 0; mo < M_DIM; mo += 32) {
        __syncthreads();
#pragma unroll 4
        for (int idx = tid; idx < 32 * C_DIM; idx += THREADS) {
            const int cc = idx & 255, mk = idx >> 8;
            ms2[mk * C_DIM + cc] = g_mem_norm[(mo + mk) * C_DIM + cc];
        }
        __syncthreads();
#pragma unroll 4
        for (int mk = 0; mk < 32; mk++) {
            const float a0 = scores[(t0 + 0) * SROW + mo + mk];
            const float a1 = scores[(t0 + 1) * SROW + mo + mk];
            const float a2 = scores[(t0 + 2) * SROW + mo + mk];
            const float a3 = scores[(t0 + 3) * SROW + mo + mk];
            const float* mrow = ms2 + mk * C_DIM + c0;
#pragma unroll
            for (int j4 = 0; j4 < 4; j4++) {
                const float4 mv = *(const float4*)&mrow[j4 * 4];
                acc2[0][j4 * 4 + 0] += a0 * mv.x; acc2[0][j4 * 4 + 1] += a0 * mv.y;
                acc2[0][j4 * 4 + 2] += a0 * mv.z; acc2[0][j4 * 4 + 3] += a0 * mv.w;
                acc2[1][j4 * 4 + 0] += a1 * mv.x; acc2[1][j4 * 4 + 1] += a1 * mv.y;
                acc2[1][j4 * 4 + 2] += a1 * mv.z; acc2[1][j4 * 4 + 3] += a1 * mv.w;
                acc2[2][j4 * 4 + 0] += a2 * mv.x; acc2[2][j4 * 4 + 1] += a2 * mv.y;
                acc2[2][j4 * 4 + 2] += a2 * mv.z; acc2[2][j4 * 4 + 3] += a2 * mv.w;
                acc2[3][j4 * 4 + 0] += a3 * mv.x; acc2[3][j4 * 4 + 1] += a3 * mv.y;
                acc2[3][j4 * 4 + 2] += a3 * mv.z; acc2[3][j4 * 4 + 3] += a3 * mv.w;
            }
        }
    }

    // ---- write output [n, c, h, w]: 4 consecutive tokens -> float4 ---------
    float* ob = out + (size_t)n * C_DIM * HW_DIM + hw0;
#pragma unroll
    for (int j = 0; j < 16; j++) {
        const float4 v = make_float4(acc2[0][j], acc2[1][j], acc2[2][j], acc2[3][j]);
        *(float4*)&ob[(size_t)(c0 + j) * HW_DIM + t0] = v;
    }
}

// ---------------------------------------------------------------------------
extern "C" void kernel_launch(void* const* d_in, const int* in_sizes, int n_in,
                              void* d_out, int out_size) {
    const float* x      = (const float*)d_in[0];  // [16,256,64,64]
    const float* memory = (const float*)d_in[1];  // [512,256]
    const float* w1     = (const float*)d_in[2];  // [256,128]
    const float* b1     = (const float*)d_in[3];  // [128]
    const float* w2     = (const float*)d_in[4];  // [128,256]
    const float* b2     = (const float*)d_in[5];  // [256]

    float* out    = (float*)d_out;                              // [16,256,64,64]
    float* attmap = out + (size_t)N_IMG * C_DIM * HW_DIM;       // [16,512,64,64]

    mem_mlp_kernel<<<M_DIM, THREADS>>>(memory, w1, b1, w2, b2);

    const size_t smem_bytes =
        (size_t)(TB * SROW + C_DIM * TB + 64 * CCHUNK + TB) * sizeof(float);
    cudaFuncSetAttribute(fused_attn_kernel,
                         cudaFuncAttributeMaxDynamicSharedMemorySize,
                         (int)smem_bytes);

    const int tiles = (N_IMG * HW_DIM) / TB;  // 1024
    fused_attn_kernel<<<tiles, THREADS, smem_bytes>>>(x, out, attmap);
}

// round 6
// speedup vs baseline: 3.1090x; 3.1059x over previous
#include <cuda_runtime.h>
#include <cuda_bf16.h>
#include <cstdint>
#include <math.h>

#define CD 256
#define MD 512
#define HWD 4096
#define NIMG 16
#define LAMBDA 0.0025f

// SMEM byte offsets
#define SC_O    0u        // scores [32][516] f32 = 66048 ; also x-stage, B2 ring, out-stage
#define B2H_O   0u
#define B2L_O   20480u
#define XA_HI   66048u    // x-hat hi [32 rows x 528B]
#define XA_LO   82944u
#define ATT_HI  66048u    // att hi [32 rows x 1040B] (aliases XA/B1 after GEMM1)
#define ATT_LO  99328u
#define B1H_O   99840u    // B1 chunk [64 rows x 528B]
#define B1L_O   133632u
#define RED_O   167424u   // 256 f32
#define INV_O   168448u   // 32 f32
#define SMEM_SZ 168576u

__device__ __nv_bfloat16 g_B1h[MD*CD], g_B1l[MD*CD];  // m-hat   [m][c]
__device__ __nv_bfloat16 g_B2h[CD*MD], g_B2l[CD*MD];  // m-hat^T [c][m]

__device__ __forceinline__ uint32_t smem_u32(const void* p) {
    uint32_t a;
    asm("{ .reg .u64 t; cvta.to.shared.u64 t, %1; cvt.u32.u64 %0, t; }" : "=r"(a) : "l"(p));
    return a;
}
#define LDSM4(r,a) asm volatile("ldmatrix.sync.aligned.m8n8.x4.shared.b16 {%0,%1,%2,%3},[%4];" \
    : "=r"((r)[0]),"=r"((r)[1]),"=r"((r)[2]),"=r"((r)[3]) : "r"(a))
#define LDSM2(r,a) asm volatile("ldmatrix.sync.aligned.m8n8.x2.shared.b16 {%0,%1},[%2];" \
    : "=r"((r)[0]),"=r"((r)[1]) : "r"(a))
#define MMA(d,a,bb) asm volatile( \
    "mma.sync.aligned.m16n8k16.row.col.f32.bf16.bf16.f32 {%0,%1,%2,%3},{%4,%5,%6,%7},{%8,%9},{%0,%1,%2,%3};" \
    : "+f"((d)[0]),"+f"((d)[1]),"+f"((d)[2]),"+f"((d)[3]) \
    : "r"((a)[0]),"r"((a)[1]),"r"((a)[2]),"r"((a)[3]),"r"((bb)[0]),"r"((bb)[1]))

__device__ __forceinline__ void pack_hl(const float* v, char* hi, char* lo) {
    uint4 h, l;
    float r[8];
#pragma unroll
    for (int j = 0; j < 8; j++) {
        float hv = __bfloat162float(__float2bfloat16(v[j]));
        r[j] = v[j] - hv;
    }
    __nv_bfloat162 h0 = __floats2bfloat162_rn(v[0], v[1]), h1 = __floats2bfloat162_rn(v[2], v[3]);
    __nv_bfloat162 h2 = __floats2bfloat162_rn(v[4], v[5]), h3 = __floats2bfloat162_rn(v[6], v[7]);
    __nv_bfloat162 l0 = __floats2bfloat162_rn(r[0], r[1]), l1 = __floats2bfloat162_rn(r[2], r[3]);
    __nv_bfloat162 l2 = __floats2bfloat162_rn(r[4], r[5]), l3 = __floats2bfloat162_rn(r[6], r[7]);
    h.x = *(uint32_t*)&h0; h.y = *(uint32_t*)&h1; h.z = *(uint32_t*)&h2; h.w = *(uint32_t*)&h3;
    l.x = *(uint32_t*)&l0; l.y = *(uint32_t*)&l1; l.z = *(uint32_t*)&l2; l.w = *(uint32_t*)&l3;
    *(uint4*)hi = h; *(uint4*)lo = l;
}

// ---------------- prologue: MLP + L2 norm + hi/lo split ----------------
__global__ void mem_mlp_kernel(const float* __restrict__ memory,
                               const float* __restrict__ w1, const float* __restrict__ b1,
                               const float* __restrict__ w2, const float* __restrict__ b2) {
    __shared__ float srow[CD], h[128], red[256];
    const int m = blockIdx.x, tid = threadIdx.x;
    srow[tid] = memory[m*CD + tid];
    __syncthreads();
    if (tid < 128) {
        float a = b1[tid];
#pragma unroll 8
        for (int c = 0; c < CD; c++) a += srow[c] * w1[c*128 + tid];
        h[tid] = fmaxf(a, 0.f);
    }
    __syncthreads();
    float a = b2[tid];
#pragma unroll 8
    for (int j = 0; j < 128; j++) a += h[j] * w2[j*CD + tid];
    a = fmaxf(a, 0.f);
    red[tid] = a*a;
    __syncthreads();
#pragma unroll
    for (int s = 128; s > 0; s >>= 1) { if (tid < s) red[tid] += red[tid+s]; __syncthreads(); }
    const float v = a / fmaxf(sqrtf(red[0]), 1e-12f);
    __nv_bfloat16 hb = __float2bfloat16(v);
    __nv_bfloat16 lb = __float2bfloat16(v - __bfloat162float(hb));
    g_B1h[m*CD + tid] = hb;  g_B1l[m*CD + tid] = lb;
    g_B2h[tid*MD + m] = hb;  g_B2l[tid*MD + m] = lb;
}

// ---------------- fused HMMA kernel: 32 tokens per CTA ----------------
__global__ __launch_bounds__(256, 1)
void fused_kernel(const float* __restrict__ x, float* __restrict__ out,
                  float* __restrict__ attmap) {
    extern __shared__ char smem[];
    float* sc = (float*)smem;
    float* red = (float*)(smem + RED_O);
    float* inv = (float*)(smem + INV_O);
    const uint32_t sb = smem_u32(smem);
    const int tid = threadIdx.x, lane = tid & 31, wid = tid >> 5;
    const int b = blockIdx.x;
    const int n = b >> 7;
    const int hw0 = (b & 127) << 5;
    const float* xb = x + (size_t)n*CD*HWD + hw0;

    // ---- stage x tile [256 c][32 t] into sc, coalesced ----
    for (int i = tid; i < CD*32; i += 256)
        sc[i] = xb[(size_t)(i >> 5)*HWD + (i & 31)];
    __syncthreads();

    // ---- token L2 norms ----
    {
        const int t = tid & 31, p = tid >> 5;
        float s = 0.f;
        for (int c = p*32; c < p*32 + 32; c++) { float v = sc[c*32 + t]; s += v*v; }
        red[p*32 + t] = s;
    }
    __syncthreads();
    if (tid < 32) {
        float s = 0.f;
        for (int p = 0; p < 8; p++) s += red[p*32 + tid];
        inv[tid] = 1.f / fmaxf(sqrtf(s), 1e-12f);
    }
    __syncthreads();

    // ---- pack x-hat hi/lo rows [t][256], rows padded to 528B ----
    for (int i = tid; i < 1024; i += 256) {
        const int t = i >> 5, ch = i & 31;
        const float iv = inv[t];
        float v[8];
#pragma unroll
        for (int j = 0; j < 8; j++) v[j] = sc[(ch*8 + j)*32 + t] * iv;
        pack_hl(v, smem + XA_HI + t*528 + ch*16, smem + XA_LO + t*528 + ch*16);
    }
    __syncthreads();

    // ---- GEMM1: scores[32 t][512 m], chunks of 64 m ----
    {
        const int tokg = wid >> 2, mg = wid & 3;
        const uint32_t arow = tokg*16 + (lane & 15);
        const uint32_t ahioff = (lane >> 4) * 16;
        for (int mo = 0; mo < 8; mo++) {
            for (int i = tid; i < 2048; i += 256) {
                const int r = i >> 5, q = i & 31;
                *(uint4*)(smem + B1H_O + r*528 + q*16) = ((const uint4*)g_B1h)[(mo*64 + r)*32 + q];
                *(uint4*)(smem + B1L_O + r*528 + q*16) = ((const uint4*)g_B1l)[(mo*64 + r)*32 + q];
            }
            __syncthreads();
            float acc[2][4] = {};
            for (int kt = 0; kt < 16; kt++) {
                const uint32_t aaddr = sb + XA_HI + arow*528 + kt*32 + ahioff;
                uint32_t ah[4], al[4];
                LDSM4(ah, aaddr); LDSM4(al, aaddr + (XA_LO - XA_HI));
#pragma unroll
                for (int j = 0; j < 2; j++) {
                    const uint32_t brow = mg*16 + j*8 + (lane & 7);
                    const uint32_t baddr = sb + B1H_O + brow*528 + kt*32 + ((lane >> 3) & 1)*16;
                    uint32_t bh[2], bl[2];
                    LDSM2(bh, baddr); LDSM2(bl, baddr + (B1L_O - B1H_O));
                    MMA(acc[j], ah, bh); MMA(acc[j], al, bh); MMA(acc[j], ah, bl);
                }
            }
            const int r0 = tokg*16 + (lane >> 2);
            const int c00 = mo*64 + mg*16 + (lane & 3)*2;
#pragma unroll
            for (int j = 0; j < 2; j++) {
                *(float2*)&sc[r0*516 + c00 + j*8]      = make_float2(acc[j][0], acc[j][1]);
                *(float2*)&sc[(r0+8)*516 + c00 + j*8]  = make_float2(acc[j][2], acc[j][3]);
            }
            __syncthreads();
        }
    }

    // ---- softmax + shrink + L1 renorm (warp -> 4 tokens) ----
    for (int rt = 0; rt < 4; rt++) {
        const int t = wid*4 + rt;
        float* row = sc + t*516;
        float e[16], s = 0.f;
#pragma unroll
        for (int k = 0; k < 16; k++) { e[k] = __expf(row[lane + 32*k]); s += e[k]; }
#pragma unroll
        for (int o = 16; o > 0; o >>= 1) s += __shfl_xor_sync(0xffffffffu, s, o);
        const float invs = 1.f / s;
        float as = 0.f;
#pragma unroll
        for (int k = 0; k < 16; k++) { e[k] = fmaxf(e[k]*invs - LAMBDA, 0.f); as += e[k]; }
#pragma unroll
        for (int o = 16; o > 0; o >>= 1) as += __shfl_xor_sync(0xffffffffu, as, o);
        const float inva = 1.f / fmaxf(as, 1e-12f);
#pragma unroll
        for (int k = 0; k < 16; k++) row[lane + 32*k] = e[k] * inva;
    }
    __syncthreads();

    // ---- attmap write (coalesced) + pack att hi/lo [t][512] ----
    float* amb = attmap + (size_t)n*MD*HWD + hw0;
    for (int i = tid; i < MD*32; i += 256) {
        const int m = i >> 5, t = i & 31;
        amb[(size_t)m*HWD + t] = sc[t*516 + m];
    }
    for (int i = tid; i < 2048; i += 256) {
        const int t = i >> 6, g = i & 63;
        float v[8];
#pragma unroll
        for (int j = 0; j < 8; j++) v[j] = sc[t*516 + g*8 + j];
        pack_hl(v, smem + ATT_HI + t*1040 + g*16, smem + ATT_LO + t*1040 + g*16);
    }
    __syncthreads();

    // ---- GEMM2: out[32 t][256 c], chunks of 32 m (k) ----
    const int tokg2 = wid & 1, cg = wid >> 1;
    float acc2[8][4] = {};
    const uint32_t arow2 = tokg2*16 + (lane & 15);
    const uint32_t ahioff = (lane >> 4) * 16;
    for (int ko = 0; ko < 16; ko++) {
        for (int i = tid; i < 1024; i += 256) {
            const int c = i >> 2, q = i & 3;
            *(uint4*)(smem + B2H_O + c*80 + q*16) = ((const uint4*)g_B2h)[c*64 + ko*4 + q];
            *(uint4*)(smem + B2L_O + c*80 + q*16) = ((const uint4*)g_B2l)[c*64 + ko*4 + q];
        }
        __syncthreads();
#pragma unroll
        for (int kt = 0; kt < 2; kt++) {
            const uint32_t aaddr = sb + ATT_HI + arow2*1040 + (ko*32 + kt*16)*2 + ahioff;
            uint32_t ah[4], al[4];
            LDSM4(ah, aaddr); LDSM4(al, aaddr + (ATT_LO - ATT_HI));
#pragma unroll
            for (int j = 0; j < 8; j++) {
                const uint32_t brow = cg*64 + j*8 + (lane & 7);
                const uint32_t baddr = sb + B2H_O + brow*80 + kt*32 + ((lane >> 3) & 1)*16;
                uint32_t bh[2], bl[2];
                LDSM2(bh, baddr); LDSM2(bl, baddr + (B2L_O - B2H_O));
                MMA(acc2[j], ah, bh); MMA(acc2[j], al, bh); MMA(acc2[j], ah, bl);
            }
        }
        __syncthreads();
    }

    // ---- stage out [t][260] in sc, then coalesced write ----
    {
        const int r0 = tokg2*16 + (lane >> 2);
#pragma unroll
        for (int j = 0; j < 8; j++) {
            const int c = cg*64 + j*8 + (lane & 3)*2;
            *(float2*)&sc[r0*260 + c]     = make_float2(acc2[j][0], acc2[j][1]);
            *(float2*)&sc[(r0+8)*260 + c] = make_float2(acc2[j][2], acc2[j][3]);
        }
    }
    __syncthreads();
    float* ob = out + (size_t)n*CD*HWD + hw0;
    for (int i = tid; i < CD*32; i += 256) {
        const int c = i >> 5, t = i & 31;
        ob[(size_t)c*HWD + t] = sc[t*260 + c];
    }
}

// ---------------------------------------------------------------------------
extern "C" void kernel_launch(void* const* d_in, const int* in_sizes, int n_in,
                              void* d_out, int out_size) {
    const float* x      = (const float*)d_in[0];
    const float* memory = (const float*)d_in[1];
    const float* w1     = (const float*)d_in[2];
    const float* b1     = (const float*)d_in[3];
    const float* w2     = (const float*)d_in[4];
    const float* b2     = (const float*)d_in[5];

    float* out    = (float*)d_out;
    float* attmap = out + (size_t)NIMG*CD*HWD;

    mem_mlp_kernel<<<MD, 256>>>(memory, w1, b1, w2, b2);

    cudaFuncSetAttribute(fused_kernel, cudaFuncAttributeMaxDynamicSharedMemorySize, SMEM_SZ);
    fused_kernel<<<1024, 256, SMEM_SZ>>>(x, out, attmap);
}

// round 7
// speedup vs baseline: 4.3939x; 1.4133x over previous
#include <cuda_runtime.h>
#include <cuda_bf16.h>
#include <cstdint>
#include <math.h>

#define CD 256
#define MD 512
#define HWD 4096
#define NIMG 16
#define LAMBDA 0.0025f
#define SROW 514

// SMEM layout (bytes)
#define SC_O   0u         // fp32 scores/att [32][514] = 65792 ; x-stage; out-stage
#define XA_HI  65792u     // x-hat hi tiles [32][528B]
#define XA_LO  82688u
#define RED_O  99584u     // 256 f32
#define INV_O  100608u    // 32 f32
#define SMEM_SZ 100736u
#define XLD    16896u     // XA_LO - XA_HI

__device__ uint2 g_B1p[MD*128];              // [m][c-pair]  (hi2, lo2)
__device__ uint2 g_B2p[CD*256];              // [c][m-pair]  (hi2, lo2)
__device__ __nv_bfloat16 g_Mh[MD*CD], g_Ml[MD*CD];

__device__ __forceinline__ uint32_t smem_u32(const void* p) {
    uint32_t a;
    asm("{ .reg .u64 t; cvta.to.shared.u64 t, %1; cvt.u32.u64 %0, t; }" : "=r"(a) : "l"(p));
    return a;
}
#define LDSM4(r,a) asm volatile("ldmatrix.sync.aligned.m8n8.x4.shared.b16 {%0,%1,%2,%3},[%4];" \
    : "=r"((r)[0]),"=r"((r)[1]),"=r"((r)[2]),"=r"((r)[3]) : "r"(a))
#define MMA(d,a,bb) asm volatile( \
    "mma.sync.aligned.m16n8k16.row.col.f32.bf16.bf16.f32 {%0,%1,%2,%3},{%4,%5,%6,%7},{%8,%9},{%0,%1,%2,%3};" \
    : "+f"((d)[0]),"+f"((d)[1]),"+f"((d)[2]),"+f"((d)[3]) \
    : "r"((a)[0]),"r"((a)[1]),"r"((a)[2]),"r"((a)[3]),"r"((bb)[0]),"r"((bb)[1]))

__device__ __forceinline__ void pack_hl(const float* v, char* hi, char* lo) {
    uint4 h, l;
    float r[8];
#pragma unroll
    for (int j = 0; j < 8; j++)
        r[j] = v[j] - __bfloat162float(__float2bfloat16(v[j]));
    __nv_bfloat162 h0 = __floats2bfloat162_rn(v[0], v[1]), h1 = __floats2bfloat162_rn(v[2], v[3]);
    __nv_bfloat162 h2 = __floats2bfloat162_rn(v[4], v[5]), h3 = __floats2bfloat162_rn(v[6], v[7]);
    __nv_bfloat162 l0 = __floats2bfloat162_rn(r[0], r[1]), l1 = __floats2bfloat162_rn(r[2], r[3]);
    __nv_bfloat162 l2 = __floats2bfloat162_rn(r[4], r[5]), l3 = __floats2bfloat162_rn(r[6], r[7]);
    h.x = *(uint32_t*)&h0; h.y = *(uint32_t*)&h1; h.z = *(uint32_t*)&h2; h.w = *(uint32_t*)&h3;
    l.x = *(uint32_t*)&l0; l.y = *(uint32_t*)&l1; l.z = *(uint32_t*)&l2; l.w = *(uint32_t*)&l3;
    *(uint4*)hi = h; *(uint4*)lo = l;
}

// cvt float2 (k,k+1) -> bf16x2 hi reg + lo reg
__device__ __forceinline__ void cvt_hl(float2 v, uint32_t& hr, uint32_t& lr) {
    __nv_bfloat162 h = __floats2bfloat162_rn(v.x, v.y);
    float2 rm = make_float2(v.x - __bfloat162float(h.x), v.y - __bfloat162float(h.y));
    __nv_bfloat162 l = __floats2bfloat162_rn(rm.x, rm.y);
    hr = *(uint32_t*)&h; lr = *(uint32_t*)&l;
}

// ---------------- prologue: MLP + L2 norm + packed hi/lo ----------------
__global__ void mem_mlp_kernel(const float* __restrict__ memory,
                               const float* __restrict__ w1, const float* __restrict__ b1,
                               const float* __restrict__ w2, const float* __restrict__ b2) {
    __shared__ float srow[CD], h[128], red[256];
    __shared__ __nv_bfloat16 shb[256], slb[256];
    const int m = blockIdx.x, tid = threadIdx.x;
    srow[tid] = memory[m*CD + tid];
    __syncthreads();
    if (tid < 128) {
        float a = b1[tid];
#pragma unroll 8
        for (int c = 0; c < CD; c++) a += srow[c] * w1[c*128 + tid];
        h[tid] = fmaxf(a, 0.f);
    }
    __syncthreads();
    float a = b2[tid];
#pragma unroll 8
    for (int j = 0; j < 128; j++) a += h[j] * w2[j*CD + tid];
    a = fmaxf(a, 0.f);
    red[tid] = a*a;
    __syncthreads();
#pragma unroll
    for (int s = 128; s > 0; s >>= 1) { if (tid < s) red[tid] += red[tid+s]; __syncthreads(); }
    const float v = a / fmaxf(sqrtf(red[0]), 1e-12f);
    __nv_bfloat16 hb = __float2bfloat16(v);
    __nv_bfloat16 lb = __float2bfloat16(v - __bfloat162float(hb));
    g_Mh[m*CD + tid] = hb;  g_Ml[m*CD + tid] = lb;
    shb[tid] = hb; slb[tid] = lb;
    __syncthreads();
    if (tid < 128) {
        __nv_bfloat162 hh, ll;
        hh.x = shb[2*tid]; hh.y = shb[2*tid+1];
        ll.x = slb[2*tid]; ll.y = slb[2*tid+1];
        g_B1p[m*128 + tid] = make_uint2(*(uint32_t*)&hh, *(uint32_t*)&ll);
    }
}

__global__ void pack2_kernel() {
    const int idx = blockIdx.x*256 + threadIdx.x;   // 65536 total
    const int c = idx >> 8, p = idx & 255;
    __nv_bfloat162 hh, ll;
    hh.x = g_Mh[(2*p)*CD + c]; hh.y = g_Mh[(2*p+1)*CD + c];
    ll.x = g_Ml[(2*p)*CD + c]; ll.y = g_Ml[(2*p+1)*CD + c];
    g_B2p[c*256 + p] = make_uint2(*(uint32_t*)&hh, *(uint32_t*)&ll);
}

// ---------------- fused HMMA kernel: 32 tokens per CTA, 2 CTA/SM ----------------
__global__ __launch_bounds__(256, 2)
void fused_kernel(const float* __restrict__ x, float* __restrict__ out,
                  float* __restrict__ attmap) {
    extern __shared__ char smem[];
    float* sc  = (float*)smem;
    float* red = (float*)(smem + RED_O);
    float* inv = (float*)(smem + INV_O);
    const uint32_t sb = smem_u32(smem);
    const int tid = threadIdx.x, lane = tid & 31, wid = tid >> 5;
    const int b = blockIdx.x;
    const int n = b >> 7;
    const int hw0 = (b & 127) << 5;
    const float* xb = x + (size_t)n*CD*HWD + hw0;

    // ---- stage x tile [256 c][32 t], coalesced ----
    for (int i = tid; i < CD*32; i += 256)
        sc[i] = xb[(size_t)(i >> 5)*HWD + (i & 31)];
    __syncthreads();

    // ---- token L2 norms ----
    {
        const int t = tid & 31, p = tid >> 5;
        float s = 0.f;
        for (int c = p*32; c < p*32 + 32; c++) { float v = sc[c*32 + t]; s += v*v; }
        red[p*32 + t] = s;
    }
    __syncthreads();
    if (tid < 32) {
        float s = 0.f;
        for (int p = 0; p < 8; p++) s += red[p*32 + tid];
        inv[tid] = 1.f / fmaxf(sqrtf(s), 1e-12f);
    }
    __syncthreads();

    // ---- pack x-hat hi/lo tiles [32 t][256 c], rows 528B ----
    for (int i = tid; i < 1024; i += 256) {
        const int t = i >> 5, ch = i & 31;
        const float iv = inv[t];
        float v[8];
#pragma unroll
        for (int j = 0; j < 8; j++) v[j] = sc[(ch*8 + j)*32 + t] * iv;
        pack_hl(v, smem + XA_HI + t*528 + ch*16, smem + XA_LO + t*528 + ch*16);
    }
    __syncthreads();

    // ---- GEMM1: each warp 32 tok x 64 m, K=256, B from global ----
    {
        const int mg = wid;                      // m base = mg*64
        float acc[2][8][4] = {};
        const uint32_t a0 = sb + XA_HI + (lane & 15)*528 + (lane >> 4)*16;
        const uint32_t a1 = a0 + 16*528;
        const uint2* bbase = g_B1p + (size_t)(mg*64 + (lane >> 2))*128 + (lane & 3);
#pragma unroll 2
        for (int kt = 0; kt < 16; kt++) {
            uint32_t ah0[4], al0[4], ah1[4], al1[4];
            LDSM4(ah0, a0 + kt*32); LDSM4(al0, a0 + kt*32 + XLD);
            LDSM4(ah1, a1 + kt*32); LDSM4(al1, a1 + kt*32 + XLD);
#pragma unroll
            for (int jj = 0; jj < 2; jj++) {
                uint2 q[8];
#pragma unroll
                for (int j = 0; j < 4; j++) {
                    const uint2* bp = bbase + (size_t)(jj*4 + j)*8*128 + kt*8;
                    q[2*j] = bp[0]; q[2*j+1] = bp[4];
                }
#pragma unroll
                for (int j = 0; j < 4; j++) {
                    uint32_t bh[2] = {q[2*j].x, q[2*j+1].x};
                    uint32_t bl[2] = {q[2*j].y, q[2*j+1].y};
                    float* c0 = acc[0][jj*4+j];
                    float* c1 = acc[1][jj*4+j];
                    MMA(c0, ah0, bh); MMA(c0, al0, bh); MMA(c0, ah0, bl);
                    MMA(c1, ah1, bh); MMA(c1, al1, bh); MMA(c1, ah1, bl);
                }
            }
        }
        // store scores
#pragma unroll
        for (int th = 0; th < 2; th++)
#pragma unroll
            for (int j = 0; j < 8; j++) {
                const int r0 = th*16 + (lane >> 2);
                const int c = mg*64 + j*8 + (lane & 3)*2;
                *(float2*)&sc[r0*SROW + c]     = make_float2(acc[th][j][0], acc[th][j][1]);
                *(float2*)&sc[(r0+8)*SROW + c] = make_float2(acc[th][j][2], acc[th][j][3]);
            }
    }
    __syncthreads();

    // ---- softmax + shrink + L1 renorm (warp -> 4 tokens), in place ----
    for (int rt = 0; rt < 4; rt++) {
        const int t = wid*4 + rt;
        float* row = sc + t*SROW;
        float e[16], s = 0.f;
#pragma unroll
        for (int k = 0; k < 16; k++) { e[k] = __expf(row[lane + 32*k]); s += e[k]; }
#pragma unroll
        for (int o = 16; o > 0; o >>= 1) s += __shfl_xor_sync(0xffffffffu, s, o);
        const float invs = 1.f / s;
        float as = 0.f;
#pragma unroll
        for (int k = 0; k < 16; k++) { e[k] = fmaxf(e[k]*invs - LAMBDA, 0.f); as += e[k]; }
#pragma unroll
        for (int o = 16; o > 0; o >>= 1) as += __shfl_xor_sync(0xffffffffu, as, o);
        const float inva = 1.f / fmaxf(as, 1e-12f);
#pragma unroll
        for (int k = 0; k < 16; k++) row[lane + 32*k] = e[k] * inva;
    }
    __syncthreads();

    // ---- attmap write (coalesced along t) ----
    float* amb = attmap + (size_t)n*MD*HWD + hw0;
    for (int i = tid; i < MD*32; i += 256) {
        const int m = i >> 5, t = i & 31;
        amb[(size_t)m*HWD + t] = sc[t*SROW + m];
    }

    // ---- GEMM2: each warp 32 tok x 32 c, K=512; A from fp32 att, B from global ----
    float acc2[2][4][4] = {};
    {
        const int cg = wid;                      // c base = cg*32
        const uint2* bbase = g_B2p + (size_t)(cg*32 + (lane >> 2))*256 + (lane & 3);
#pragma unroll 2
        for (int kt = 0; kt < 32; kt++) {
            uint32_t ah[2][4], al[2][4];
#pragma unroll
            for (int th = 0; th < 2; th++) {
                const int r = th*16 + (lane >> 2);
                const int k0 = kt*16 + (lane & 3)*2;
                float2 v0 = *(float2*)&sc[r*SROW + k0];
                float2 v1 = *(float2*)&sc[(r+8)*SROW + k0];
                float2 v2 = *(float2*)&sc[r*SROW + k0 + 8];
                float2 v3 = *(float2*)&sc[(r+8)*SROW + k0 + 8];
                cvt_hl(v0, ah[th][0], al[th][0]);
                cvt_hl(v1, ah[th][1], al[th][1]);
                cvt_hl(v2, ah[th][2], al[th][2]);
                cvt_hl(v3, ah[th][3], al[th][3]);
            }
            uint2 q[8];
#pragma unroll
            for (int j = 0; j < 4; j++) {
                const uint2* bp = bbase + (size_t)j*8*256 + kt*8;
                q[2*j] = bp[0]; q[2*j+1] = bp[4];
            }
#pragma unroll
            for (int j = 0; j < 4; j++) {
                uint32_t bh[2] = {q[2*j].x, q[2*j+1].x};
                uint32_t bl[2] = {q[2*j].y, q[2*j+1].y};
#pragma unroll
                for (int th = 0; th < 2; th++) {
                    float* c0 = acc2[th][j];
                    MMA(c0, ah[th], bh); MMA(c0, al[th], bh); MMA(c0, ah[th], bl);
                }
            }
        }
    }
    __syncthreads();   // all warps done reading sc

    // ---- stage out [32 t][260] over sc, then coalesced write ----
    {
        const int cg = wid;
#pragma unroll
        for (int th = 0; th < 2; th++)
#pragma unroll
            for (int j = 0; j < 4; j++) {
                const int r0 = th*16 + (lane >> 2);
                const int c = cg*32 + j*8 + (lane & 3)*2;
                *(float2*)&sc[r0*260 + c]     = make_float2(acc2[th][j][0], acc2[th][j][1]);
                *(float2*)&sc[(r0+8)*260 + c] = make_float2(acc2[th][j][2], acc2[th][j][3]);
            }
    }
    __syncthreads();
    float* ob = out + (size_t)n*CD*HWD + hw0;
    for (int i = tid; i < CD*32; i += 256) {
        const int c = i >> 5, t = i & 31;
        ob[(size_t)c*HWD + t] = sc[t*260 + c];
    }
}

// ---------------------------------------------------------------------------
extern "C" void kernel_launch(void* const* d_in, const int* in_sizes, int n_in,
                              void* d_out, int out_size) {
    const float* x      = (const float*)d_in[0];
    const float* memory = (const float*)d_in[1];
    const float* w1     = (const float*)d_in[2];
    const float* b1     = (const float*)d_in[3];
    const float* w2     = (const float*)d_in[4];
    const float* b2     = (const float*)d_in[5];

    float* out    = (float*)d_out;
    float* attmap = out + (size_t)NIMG*CD*HWD;

    mem_mlp_kernel<<<MD, 256>>>(memory, w1, b1, w2, b2);
    pack2_kernel<<<256, 256>>>();

    cudaFuncSetAttribute(fused_kernel, cudaFuncAttributeMaxDynamicSharedMemorySize, SMEM_SZ);
    fused_kernel<<<1024, 256, SMEM_SZ>>>(x, out, attmap);
}